// round 15
// baseline (speedup 1.0000x reference)
#include <cuda_runtime.h>
#include <math.h>

#define SS 64
#define BB 32
#define HH 512
#define EE 512
#define VV 32000
#define LL 2
#define SB (SS*BB)   // 2048
#define NBLK 128

// -------- scratch (no allocation allowed; device globals instead) --------
__device__ float g_x[SB*HH];
__device__ float g_y[SB*HH];
__device__ float g_gates[3*SB*HH];
__device__ float g_wr[VV*HH];        // tf32-rounded Wout (65.5 MB)
__device__ float g_nudge[32];

// per-(bg,jg) sequence flags: one 128B line per bg. Zero-init; monotone
// across launches/replays — consumers compare RELATIVE to launch-start F0.
struct __align__(128) FlagLine { unsigned v[32]; };
__device__ FlagLine g_flag[4];

// ---------------------------- profiler nudge ----------------------------
__global__ void nudge_kernel()
{
    if (threadIdx.x < 32) g_nudge[threadIdx.x] = 0.f;
}

// ---------------------------- embedding ---------------------------------
__global__ void embed_kernel(const int* __restrict__ inputs,
                             const float* __restrict__ emb,
                             float* __restrict__ out)
{
    int row = blockIdx.x;
    int tok = inputs[row];
    const float4* src = (const float4*)(emb + (size_t)tok * EE);
    float4* dst = (float4*)(out + (size_t)row * EE);
    dst[threadIdx.x] = src[threadIdx.x];
}

// ---------------------- tf32 rne pre-rounding ----------------------------
__device__ __forceinline__ unsigned f2tf(float x)
{
    unsigned r;
    asm("cvt.rna.tf32.f32 %0, %1;" : "=r"(r) : "f"(x));
    return r;
}

__global__ void round_tf32_kernel(const float* __restrict__ src,
                                  float* __restrict__ dst, int n4)
{
    int i = blockIdx.x * blockDim.x + threadIdx.x;
    int stride = gridDim.x * blockDim.x;
    for (; i < n4; i += stride) {
        float4 v = ((const float4*)src)[i];
        uint4 u;
        u.x = f2tf(v.x); u.y = f2tf(v.y); u.z = f2tf(v.z); u.w = f2tf(v.w);
        ((uint4*)dst)[i] = u;
    }
}

// ------------- tf32 GEMM for projections (R7 config, unchanged) ----------
__device__ __forceinline__ void gemm_tf32_body(
    unsigned* __restrict__ As, unsigned* __restrict__ Bs,   // each 2*128*16
    const float* __restrict__ A, const float* __restrict__ W,
    const float* __restrict__ bias, float* __restrict__ C,
    int M, int N, int K)
{
    const int tid  = threadIdx.x;
    const int lane = tid & 31;
    const int warp = tid >> 5;
    const int wm = (warp >> 1) * 64;
    const int wn = (warp & 1) * 64;
    const int m0 = blockIdx.y * 128;
    const int n0 = blockIdx.x * 128;
    const int fr = lane >> 2;
    const int fc = lane & 3;
    const int cm  = tid >> 2;
    const int cc2 = tid & 3;

    float acc[4][8][4];
#pragma unroll
    for (int mt = 0; mt < 4; ++mt)
#pragma unroll
        for (int nt = 0; nt < 8; ++nt)
#pragma unroll
            for (int q = 0; q < 4; ++q) acc[mt][nt][q] = 0.f;

    float4 ra[4], rb[4];

#define LD_STAGE(k0)                                                          \
    {                                                                         \
        _Pragma("unroll")                                                     \
        for (int i = 0; i < 4; ++i) {                                         \
            int m = i * 32 + cm;                                              \
            ra[i] = *(const float4*)&A[(size_t)(m0 + m) * K + (k0) + cc2*4];  \
            rb[i] = *(const float4*)&W[(size_t)(n0 + m) * K + (k0) + cc2*4];  \
        }                                                                     \
    }

#define ST_STAGE(buf)                                                         \
    {                                                                         \
        _Pragma("unroll")                                                     \
        for (int i = 0; i < 4; ++i) {                                         \
            int m = i * 32 + cm;                                              \
            int off = (buf) * 2048 + m * 16 + ((cc2 ^ (m & 3)) << 2);         \
            uint4 ua; ua.x = f2tf(ra[i].x); ua.y = f2tf(ra[i].y);             \
            ua.z = f2tf(ra[i].z); ua.w = f2tf(ra[i].w);                       \
            uint4 ub; ub.x = f2tf(rb[i].x); ub.y = f2tf(rb[i].y);             \
            ub.z = f2tf(rb[i].z); ub.w = f2tf(rb[i].w);                       \
            *(uint4*)&As[off] = ua;                                           \
            *(uint4*)&Bs[off] = ub;                                           \
        }                                                                     \
    }

    LD_STAGE(0);
    ST_STAGE(0);
    __syncthreads();

    const int nstages = K / 16;
    for (int s = 0; s < nstages; ++s) {
        const int buf = s & 1;
        if (s + 1 < nstages) LD_STAGE((s + 1) * 16);

#pragma unroll
        for (int k8 = 0; k8 < 2; ++k8) {
            unsigned af[4][4], bf[8][2];
#pragma unroll
            for (int mt = 0; mt < 4; ++mt) {
                int r1 = wm + mt * 16 + fr;
                int r2 = r1 + 8;
                af[mt][0] = As[buf*2048 + r1*16 + (((k8*2+0) ^ (r1&3)) << 2) + fc];
                af[mt][1] = As[buf*2048 + r2*16 + (((k8*2+0) ^ (r2&3)) << 2) + fc];
                af[mt][2] = As[buf*2048 + r1*16 + (((k8*2+1) ^ (r1&3)) << 2) + fc];
                af[mt][3] = As[buf*2048 + r2*16 + (((k8*2+1) ^ (r2&3)) << 2) + fc];
            }
#pragma unroll
            for (int nt = 0; nt < 8; ++nt) {
                int n = wn + nt * 8 + fr;
                bf[nt][0] = Bs[buf*2048 + n*16 + (((k8*2+0) ^ (n&3)) << 2) + fc];
                bf[nt][1] = Bs[buf*2048 + n*16 + (((k8*2+1) ^ (n&3)) << 2) + fc];
            }
#pragma unroll
            for (int mt = 0; mt < 4; ++mt)
#pragma unroll
                for (int nt = 0; nt < 8; ++nt) {
                    asm volatile(
                        "mma.sync.aligned.m16n8k8.row.col.f32.tf32.tf32.f32 "
                        "{%0,%1,%2,%3}, {%4,%5,%6,%7}, {%8,%9}, {%0,%1,%2,%3};"
                        : "+f"(acc[mt][nt][0]), "+f"(acc[mt][nt][1]),
                          "+f"(acc[mt][nt][2]), "+f"(acc[mt][nt][3])
                        : "r"(af[mt][0]), "r"(af[mt][1]),
                          "r"(af[mt][2]), "r"(af[mt][3]),
                          "r"(bf[nt][0]), "r"(bf[nt][1]));
                }
        }
        if (s + 1 < nstages) ST_STAGE(buf ^ 1);
        __syncthreads();
    }
#undef LD_STAGE
#undef ST_STAGE

#pragma unroll
    for (int mt = 0; mt < 4; ++mt) {
        int row = m0 + wm + mt * 16 + fr;
#pragma unroll
        for (int nt = 0; nt < 8; ++nt) {
            int col = n0 + wn + nt * 8 + fc * 2;
            float bv0 = bias[col], bv1 = bias[col + 1];
            float2 v0; v0.x = acc[mt][nt][0] + bv0; v0.y = acc[mt][nt][1] + bv1;
            float2 v1; v1.x = acc[mt][nt][2] + bv0; v1.y = acc[mt][nt][3] + bv1;
            *(float2*)&C[(size_t)row * N + col] = v0;
            *(float2*)&C[(size_t)(row + 8) * N + col] = v1;
        }
    }
}

__global__ __launch_bounds__(128) void gemm_tf32_nt_bias3(
    const float* __restrict__ A,
    const float* __restrict__ W0, const float* __restrict__ W1, const float* __restrict__ W2,
    const float* __restrict__ b0, const float* __restrict__ b1, const float* __restrict__ b2,
    float* __restrict__ C0, float* __restrict__ C1, float* __restrict__ C2,
    int M, int N, int K)
{
    __shared__ unsigned As[2 * 2048];
    __shared__ unsigned Bs[2 * 2048];
    const float* W    = (blockIdx.z == 0) ? W0 : (blockIdx.z == 1) ? W1 : W2;
    const float* bias = (blockIdx.z == 0) ? b0 : (blockIdx.z == 1) ? b1 : b2;
    float* C          = (blockIdx.z == 0) ? C0 : (blockIdx.z == 1) ? C1 : C2;
    gemm_tf32_body(As, Bs, A, W, bias, C, M, N, K);
}

// -------- logits GEMM v2 (R14 winner, unchanged) --------------------------
__device__ __forceinline__ unsigned smem_addr_u32(const void* p)
{
    unsigned a;
    asm("{ .reg .u64 t; cvta.to.shared.u64 t, %1; cvt.u32.u64 %0, t; }"
        : "=r"(a) : "l"(p));
    return a;
}

__global__ __launch_bounds__(256) void gemm_tf32_logits(
    const float* __restrict__ A,    // [SB,512]  tf32-rounded
    const float* __restrict__ W,    // [VV,512]  tf32-rounded
    const float* __restrict__ bias,
    float* __restrict__ C)          // [SB,VV]
{
    extern __shared__ unsigned smx[];
    unsigned* As = smx;               // [2][128*32]
    unsigned* Bs = smx + 2 * 4096;    // [2][256*32]

    const int tid  = threadIdx.x;
    const int lane = tid & 31;
    const int warp = tid >> 5;        // 0..7
    const int wm = (warp >> 2) * 64;  // 2 m-warp rows
    const int wn = (warp & 3) * 64;   // 4 n-warp cols
    const int m0 = blockIdx.y * 128;
    const int n0 = blockIdx.x * 256;
    const int fr = lane >> 2;
    const int fc = lane & 3;

    float acc[4][8][4];
#pragma unroll
    for (int mt = 0; mt < 4; ++mt)
#pragma unroll
        for (int nt = 0; nt < 8; ++nt)
#pragma unroll
            for (int q = 0; q < 4; ++q) acc[mt][nt][q] = 0.f;

#define CP_STAGE(buf, k0)                                                     \
    {                                                                         \
        _Pragma("unroll")                                                     \
        for (int it = 0; it < 4; ++it) {                                      \
            int c = tid + it * 256;                                           \
            int r = c >> 3, ch = c & 7;                                       \
            unsigned d = smem_addr_u32(                                       \
                &As[(buf) * 4096 + r * 32 + ((ch ^ (r & 7)) << 2)]);          \
            const float* sp = A + (size_t)(m0 + r) * 512 + (k0) + ch * 4;     \
            asm volatile("cp.async.cg.shared.global [%0], [%1], 16;"          \
                         :: "r"(d), "l"(sp));                                 \
        }                                                                     \
        _Pragma("unroll")                                                     \
        for (int it = 0; it < 8; ++it) {                                      \
            int c = tid + it * 256;                                           \
            int r = c >> 3, ch = c & 7;                                       \
            unsigned d = smem_addr_u32(                                       \
                &Bs[(buf) * 8192 + r * 32 + ((ch ^ (r & 7)) << 2)]);          \
            const float* sp = W + (size_t)(n0 + r) * 512 + (k0) + ch * 4;     \
            asm volatile("cp.async.cg.shared.global [%0], [%1], 16;"          \
                         :: "r"(d), "l"(sp));                                 \
        }                                                                     \
        asm volatile("cp.async.commit_group;");                               \
    }

    CP_STAGE(0, 0)
    asm volatile("cp.async.wait_group 0;");
    __syncthreads();

    const int nstages = 512 / 32;    // 16
    for (int s = 0; s < nstages; ++s) {
        const int buf = s & 1;
        if (s + 1 < nstages) CP_STAGE(buf ^ 1, (s + 1) * 32)

#pragma unroll
        for (int k8 = 0; k8 < 4; ++k8) {
            const int ch0 = k8 * 2, ch1 = k8 * 2 + 1;
            unsigned af[4][4], bf[8][2];
#pragma unroll
            for (int mt = 0; mt < 4; ++mt) {
                int r1 = wm + mt * 16 + fr;
                int r2 = r1 + 8;
                af[mt][0] = As[buf*4096 + r1*32 + ((ch0 ^ (r1&7)) << 2) + fc];
                af[mt][1] = As[buf*4096 + r2*32 + ((ch0 ^ (r2&7)) << 2) + fc];
                af[mt][2] = As[buf*4096 + r1*32 + ((ch1 ^ (r1&7)) << 2) + fc];
                af[mt][3] = As[buf*4096 + r2*32 + ((ch1 ^ (r2&7)) << 2) + fc];
            }
#pragma unroll
            for (int nt = 0; nt < 8; ++nt) {
                int n = wn + nt * 8 + fr;
                bf[nt][0] = Bs[buf*8192 + n*32 + ((ch0 ^ (n&7)) << 2) + fc];
                bf[nt][1] = Bs[buf*8192 + n*32 + ((ch1 ^ (n&7)) << 2) + fc];
            }
#pragma unroll
            for (int mt = 0; mt < 4; ++mt)
#pragma unroll
                for (int nt = 0; nt < 8; ++nt) {
                    asm volatile(
                        "mma.sync.aligned.m16n8k8.row.col.f32.tf32.tf32.f32 "
                        "{%0,%1,%2,%3}, {%4,%5,%6,%7}, {%8,%9}, {%0,%1,%2,%3};"
                        : "+f"(acc[mt][nt][0]), "+f"(acc[mt][nt][1]),
                          "+f"(acc[mt][nt][2]), "+f"(acc[mt][nt][3])
                        : "r"(af[mt][0]), "r"(af[mt][1]),
                          "r"(af[mt][2]), "r"(af[mt][3]),
                          "r"(bf[nt][0]), "r"(bf[nt][1]));
                }
        }
        asm volatile("cp.async.wait_group 0;");
        __syncthreads();
    }
#undef CP_STAGE

#pragma unroll
    for (int mt = 0; mt < 4; ++mt) {
        int row = m0 + wm + mt * 16 + fr;
#pragma unroll
        for (int nt = 0; nt < 8; ++nt) {
            int col = n0 + wn + nt * 8 + fc * 2;
            float bv0 = bias[col], bv1 = bias[col + 1];
            float2 v0; v0.x = acc[mt][nt][0] + bv0; v0.y = acc[mt][nt][1] + bv1;
            float2 v1; v1.x = acc[mt][nt][2] + bv0; v1.y = acc[mt][nt][3] + bv1;
            *(float2*)&C[(size_t)row * VV + col] = v0;
            *(float2*)&C[(size_t)(row + 8) * VV + col] = v1;
        }
    }
}

// ------- persistent GRU scan v10: de-staged (direct L2 reads) ------------
// 128 blocks = 32 jg x 4 bg, one-hop flag sync (R13). h is read DIRECTLY
// from global via __ldcg inside the FMA loop (32 independent float4 loads
// per warp -> MLP hides L2 latency). smem staging + 2 syncthreads removed.
__device__ __forceinline__ void fma2(unsigned long long& a,
                                     unsigned long long x, unsigned long long h)
{
    asm("fma.rn.f32x2 %0, %1, %2, %0;" : "+l"(a) : "l"(x), "l"(h));
}

__global__ __launch_bounds__(512, 1) void gru_scan_kernel(
    const float* __restrict__ gates,   // [3][SB][HH]
    const float* __restrict__ Wr,
    const float* __restrict__ Wz,
    const float* __restrict__ Wh,
    const float* __restrict__ h0,      // [BB][HH]
    float* __restrict__ hs_out,        // [SS][BB][HH]
    float* __restrict__ hfin)          // [BB][HH] or null
{
    extern __shared__ float sm[];
    float* red = sm;                       // [16][24][33]
    unsigned* sF0 = (unsigned*)(red + 16 * 24 * 33);

    const int tid  = threadIdx.x;
    const int lane = tid & 31;
    const int w    = tid >> 5;             // 0..15 = jl
    const int bid  = blockIdx.x;
    const int jg   = bid >> 2;             // 0..31
    const int bg   = bid & 3;              // 0..3
    const int j    = jg * 16 + w;

    unsigned* flags = &g_flag[bg].v[0];

    if (tid == 0) sF0[0] = flags[jg];

    // hoist this warp's 3 weight rows into registers
    ulonglong2 wv[3][4];
    {
        const float* W0 = Wr + (size_t)j * HH;
        const float* W1 = Wz + (size_t)j * HH;
        const float* W2 = Wh + (size_t)j * HH;
#pragma unroll
        for (int i = 0; i < 4; ++i) {
            int kof = 4 * lane + 128 * i;
            wv[0][i] = *(const ulonglong2*)&W0[kof];
            wv[1][i] = *(const ulonglong2*)&W1[kof];
            wv[2][i] = *(const ulonglong2*)&W2[kof];
        }
    }
    __syncthreads();
    const unsigned F0 = sF0[0];

    const int b = bg * 8 + (lane & 7);     // output batch for lanes<8

    float xr = 0.f, xz = 0.f, xh = 0.f;
    if (lane < 8) {
        size_t idx = (size_t)(0 * BB + b) * HH + j;
        xr = __ldcg(&gates[idx]);
        xz = __ldcg(&gates[(size_t)SB * HH + idx]);
        xh = __ldcg(&gates[(size_t)2 * SB * HH + idx]);
    }

    for (int s = 0; s < SS; ++s) {
        const float* hsrc = (s == 0) ? h0 : hs_out + (size_t)(s - 1) * BB * HH;
        float* hdst = hs_out + (size_t)s * BB * HH;

        // ---- one-hop sync: wait for all 32 producers of this bg ----
        if (s > 0) {
            if (w == 0) {
                const unsigned target = F0 + (unsigned)s;
                unsigned v;
                bool ok;
                do {
                    asm volatile("ld.acquire.gpu.u32 %0, [%1];"
                                 : "=r"(v) : "l"(flags + lane) : "memory");
                    ok = __all_sync(0xffffffffu, (int)(v - target) >= 0);
                } while (!ok);
            }
            __syncthreads();
        }

        // ---- dot products straight from L2 (.cg), 32 indep loads/warp ----
        unsigned long long acc[3][8];
#pragma unroll
        for (int g = 0; g < 3; ++g)
#pragma unroll
            for (int c = 0; c < 8; ++c) acc[g][c] = 0ULL;

        // hold value for output lanes (issued early, consumed at the end)
        float hold = 0.f;
        if (lane < 8) hold = __ldcg(&hsrc[(size_t)b * HH + j]);

#pragma unroll
        for (int i = 0; i < 4; ++i) {
            const int kof = 4 * lane + 128 * i;
            const float* hp = hsrc + kof + (size_t)(bg * 8) * HH;
#pragma unroll
            for (int c = 0; c < 8; ++c) {
                float4 hf = __ldcg((const float4*)(hp + (size_t)c * HH));
                ulonglong2 hv = *(ulonglong2*)&hf;
                fma2(acc[0][c], wv[0][i].x, hv.x);
                fma2(acc[0][c], wv[0][i].y, hv.y);
                fma2(acc[1][c], wv[1][i].x, hv.x);
                fma2(acc[1][c], wv[1][i].y, hv.y);
                fma2(acc[2][c], wv[2][i].x, hv.x);
                fma2(acc[2][c], wv[2][i].y, hv.y);
            }
        }

        // ---- cross-lane reduce via smem transpose ----
#pragma unroll
        for (int g = 0; g < 3; ++g)
#pragma unroll
            for (int c = 0; c < 8; ++c) {
                float2 f = *(float2*)&acc[g][c];
                red[(w * 24 + g * 8 + c) * 33 + lane] = f.x + f.y;
            }
        __syncwarp();

        float sum = 0.f;
        if (lane < 24) {
            int base = (w * 24 + lane) * 33;
#pragma unroll
            for (int i = 0; i < 32; ++i) sum += red[base + i];
        }
        float s0 = __shfl_sync(0xffffffffu, sum, (lane & 7));
        float s1 = __shfl_sync(0xffffffffu, sum, 8 + (lane & 7));
        float s2 = __shfl_sync(0xffffffffu, sum, 16 + (lane & 7));

        if (lane < 8) {
            float r  = 1.f / (1.f + __expf(-(xr + s0)));
            float z  = 1.f / (1.f + __expf(-(xz + s1)));
            float hc = tanhf(xh + r * s2);
            float hn = (1.f - z) * hc + z * hold;
            hdst[(size_t)b * HH + j] = hn;
            if (s == SS - 1 && hfin) hfin[(size_t)b * HH + j] = hn;
        }

        // gate prefetch for next step (off critical path)
        if (lane < 8 && s + 1 < SS) {
            size_t idx = (size_t)((s + 1) * BB + b) * HH + j;
            xr = __ldcg(&gates[idx]);
            xz = __ldcg(&gates[(size_t)SB * HH + idx]);
            xh = __ldcg(&gates[(size_t)2 * SB * HH + idx]);
        }

        // ---- publish: all h-stores done -> release flag (one hop) ----
        __syncthreads();
        if (tid == 0) {
            asm volatile("st.release.gpu.u32 [%0], %1;"
                         :: "l"(flags + jg), "r"(F0 + (unsigned)s + 1u)
                         : "memory");
        }
    }
}

// ------------------------------ driver ----------------------------------
extern "C" void kernel_launch(void* const* d_in, const int* in_sizes, int n_in,
                              void* d_out, int out_size)
{
    const int*   inputs = (const int*)d_in[0];
    const float* hidden = (const float*)d_in[1];
    const float* emb    = (const float*)d_in[2];
    const float* Wir    = (const float*)d_in[3];
    const float* bir    = (const float*)d_in[4];
    const float* Wiz    = (const float*)d_in[5];
    const float* biz    = (const float*)d_in[6];
    const float* Wih    = (const float*)d_in[7];
    const float* bih    = (const float*)d_in[8];
    const float* Whr    = (const float*)d_in[9];
    const float* Whz    = (const float*)d_in[10];
    const float* Whh    = (const float*)d_in[11];
    const float* Wout   = (const float*)d_in[12];
    const float* bout   = (const float*)d_in[13];
    float* out = (float*)d_out;

    float *px, *py, *pg, *pwr;
    cudaGetSymbolAddress((void**)&px, g_x);
    cudaGetSymbolAddress((void**)&py, g_y);
    cudaGetSymbolAddress((void**)&pg, g_gates);
    cudaGetSymbolAddress((void**)&pwr, g_wr);

    const size_t logits_elems = (size_t)SB * VV;
    float* hfin_base = nullptr;
    if ((size_t)out_size >= logits_elems + (size_t)LL * BB * HH)
        hfin_base = out + logits_elems;

    const int smem_scan = (16 * 24 * 33) * sizeof(float) + 16;
    cudaFuncSetAttribute(gru_scan_kernel,
                         cudaFuncAttributeMaxDynamicSharedMemorySize, smem_scan);
    const int smem_log = (2 * 4096 + 2 * 8192) * sizeof(unsigned);  // 96KB
    cudaFuncSetAttribute(gemm_tf32_logits,
                         cudaFuncAttributeMaxDynamicSharedMemorySize, smem_log);

    // 0) profiler-window nudge (keeps -s 5 landing on the scan)
    nudge_kernel<<<1, 32>>>();

    // 1) embedding
    embed_kernel<<<SB, 128>>>(inputs, emb, px);

    const size_t CHNK = (size_t)SB * HH;
    for (int l = 0; l < LL; ++l) {
        float* in   = (l == 0) ? px : py;
        float* outb = (l == 0) ? py : px;

        // 2) fused input projections (tf32 mma, gate = blockIdx.z)
        dim3 gProj(HH / 128, SB / 128, 3);   // (4, 16, 3)
        gemm_tf32_nt_bias3<<<gProj, 128>>>(
            in,
            Wir + (size_t)l * HH * EE, Wiz + (size_t)l * HH * EE, Wih + (size_t)l * HH * EE,
            bir + l * HH, biz + l * HH, bih + l * HH,
            pg + 0 * CHNK, pg + 1 * CHNK, pg + 2 * CHNK,
            SB, HH, EE);

        // 3) persistent scan over all 64 steps (de-staged, one-hop sync)
        gru_scan_kernel<<<NBLK, 512, smem_scan>>>(
            pg,
            Whr + (size_t)l * HH * HH,
            Whz + (size_t)l * HH * HH,
            Whh + (size_t)l * HH * HH,
            hidden + (size_t)l * BB * HH,
            outb,
            hfin_base ? hfin_base + (size_t)l * BB * HH : nullptr);
    }

    // 4) pre-round logits operands to tf32-rne
    round_tf32_kernel<<<2048, 256>>>(Wout, pwr, VV * HH / 4);
    round_tf32_kernel<<<512, 256>>>(px, px, SB * HH / 4);

    // 5) logits GEMM v2 (cp.async, 128x256 tile, 8 warps)
    dim3 gLog(VV / 256, SB / 128);   // (125, 16)
    gemm_tf32_logits<<<gLog, 256, smem_log>>>(px, pwr, bout, out);
}

// round 16
// speedup vs baseline: 1.3404x; 1.3404x over previous
#include <cuda_runtime.h>
#include <math.h>

#define SS 64
#define BB 32
#define HH 512
#define EE 512
#define VV 32000
#define LL 2
#define SB (SS*BB)   // 2048
#define NBLK 128
#define HSTRIDE 520  // 512 + 8 pad

// -------- scratch (no allocation allowed; device globals instead) --------
__device__ float g_x[SB*HH];
__device__ float g_y[SB*HH];
__device__ float g_gates[3*SB*HH];
__device__ float g_wr[VV*HH];        // tf32-rounded Wout (65.5 MB)
__device__ float g_nudge[32];

// per-(bg,jg) sequence flags: one 128B line per bg. Zero-init; monotone
// across launches/replays — consumers compare RELATIVE to launch-start F0.
struct __align__(128) FlagLine { unsigned v[32]; };
__device__ FlagLine g_flag[4];

// ---------------------------- profiler nudge ----------------------------
__global__ void nudge_kernel()
{
    if (threadIdx.x < 32) g_nudge[threadIdx.x] = 0.f;
}

// ---------------------------- embedding ---------------------------------
__global__ void embed_kernel(const int* __restrict__ inputs,
                             const float* __restrict__ emb,
                             float* __restrict__ out)
{
    int row = blockIdx.x;
    int tok = inputs[row];
    const float4* src = (const float4*)(emb + (size_t)tok * EE);
    float4* dst = (float4*)(out + (size_t)row * EE);
    dst[threadIdx.x] = src[threadIdx.x];
}

// ---------------------- tf32 rne pre-rounding ----------------------------
__device__ __forceinline__ unsigned f2tf(float x)
{
    unsigned r;
    asm("cvt.rna.tf32.f32 %0, %1;" : "=r"(r) : "f"(x));
    return r;
}

__global__ void round_tf32_kernel(const float* __restrict__ src,
                                  float* __restrict__ dst, int n4)
{
    int i = blockIdx.x * blockDim.x + threadIdx.x;
    int stride = gridDim.x * blockDim.x;
    for (; i < n4; i += stride) {
        float4 v = ((const float4*)src)[i];
        uint4 u;
        u.x = f2tf(v.x); u.y = f2tf(v.y); u.z = f2tf(v.z); u.w = f2tf(v.w);
        ((uint4*)dst)[i] = u;
    }
}

// ------------- tf32 GEMM for projections (R7 config, unchanged) ----------
__device__ __forceinline__ void gemm_tf32_body(
    unsigned* __restrict__ As, unsigned* __restrict__ Bs,   // each 2*128*16
    const float* __restrict__ A, const float* __restrict__ W,
    const float* __restrict__ bias, float* __restrict__ C,
    int M, int N, int K)
{
    const int tid  = threadIdx.x;
    const int lane = tid & 31;
    const int warp = tid >> 5;
    const int wm = (warp >> 1) * 64;
    const int wn = (warp & 1) * 64;
    const int m0 = blockIdx.y * 128;
    const int n0 = blockIdx.x * 128;
    const int fr = lane >> 2;
    const int fc = lane & 3;
    const int cm  = tid >> 2;
    const int cc2 = tid & 3;

    float acc[4][8][4];
#pragma unroll
    for (int mt = 0; mt < 4; ++mt)
#pragma unroll
        for (int nt = 0; nt < 8; ++nt)
#pragma unroll
            for (int q = 0; q < 4; ++q) acc[mt][nt][q] = 0.f;

    float4 ra[4], rb[4];

#define LD_STAGE(k0)                                                          \
    {                                                                         \
        _Pragma("unroll")                                                     \
        for (int i = 0; i < 4; ++i) {                                         \
            int m = i * 32 + cm;                                              \
            ra[i] = *(const float4*)&A[(size_t)(m0 + m) * K + (k0) + cc2*4];  \
            rb[i] = *(const float4*)&W[(size_t)(n0 + m) * K + (k0) + cc2*4];  \
        }                                                                     \
    }

#define ST_STAGE(buf)                                                         \
    {                                                                         \
        _Pragma("unroll")                                                     \
        for (int i = 0; i < 4; ++i) {                                         \
            int m = i * 32 + cm;                                              \
            int off = (buf) * 2048 + m * 16 + ((cc2 ^ (m & 3)) << 2);         \
            uint4 ua; ua.x = f2tf(ra[i].x); ua.y = f2tf(ra[i].y);             \
            ua.z = f2tf(ra[i].z); ua.w = f2tf(ra[i].w);                       \
            uint4 ub; ub.x = f2tf(rb[i].x); ub.y = f2tf(rb[i].y);             \
            ub.z = f2tf(rb[i].z); ub.w = f2tf(rb[i].w);                       \
            *(uint4*)&As[off] = ua;                                           \
            *(uint4*)&Bs[off] = ub;                                           \
        }                                                                     \
    }

    LD_STAGE(0);
    ST_STAGE(0);
    __syncthreads();

    const int nstages = K / 16;
    for (int s = 0; s < nstages; ++s) {
        const int buf = s & 1;
        if (s + 1 < nstages) LD_STAGE((s + 1) * 16);

#pragma unroll
        for (int k8 = 0; k8 < 2; ++k8) {
            unsigned af[4][4], bf[8][2];
#pragma unroll
            for (int mt = 0; mt < 4; ++mt) {
                int r1 = wm + mt * 16 + fr;
                int r2 = r1 + 8;
                af[mt][0] = As[buf*2048 + r1*16 + (((k8*2+0) ^ (r1&3)) << 2) + fc];
                af[mt][1] = As[buf*2048 + r2*16 + (((k8*2+0) ^ (r2&3)) << 2) + fc];
                af[mt][2] = As[buf*2048 + r1*16 + (((k8*2+1) ^ (r1&3)) << 2) + fc];
                af[mt][3] = As[buf*2048 + r2*16 + (((k8*2+1) ^ (r2&3)) << 2) + fc];
            }
#pragma unroll
            for (int nt = 0; nt < 8; ++nt) {
                int n = wn + nt * 8 + fr;
                bf[nt][0] = Bs[buf*2048 + n*16 + (((k8*2+0) ^ (n&3)) << 2) + fc];
                bf[nt][1] = Bs[buf*2048 + n*16 + (((k8*2+1) ^ (n&3)) << 2) + fc];
            }
#pragma unroll
            for (int mt = 0; mt < 4; ++mt)
#pragma unroll
                for (int nt = 0; nt < 8; ++nt) {
                    asm volatile(
                        "mma.sync.aligned.m16n8k8.row.col.f32.tf32.tf32.f32 "
                        "{%0,%1,%2,%3}, {%4,%5,%6,%7}, {%8,%9}, {%0,%1,%2,%3};"
                        : "+f"(acc[mt][nt][0]), "+f"(acc[mt][nt][1]),
                          "+f"(acc[mt][nt][2]), "+f"(acc[mt][nt][3])
                        : "r"(af[mt][0]), "r"(af[mt][1]),
                          "r"(af[mt][2]), "r"(af[mt][3]),
                          "r"(bf[nt][0]), "r"(bf[nt][1]));
                }
        }
        if (s + 1 < nstages) ST_STAGE(buf ^ 1);
        __syncthreads();
    }
#undef LD_STAGE
#undef ST_STAGE

#pragma unroll
    for (int mt = 0; mt < 4; ++mt) {
        int row = m0 + wm + mt * 16 + fr;
#pragma unroll
        for (int nt = 0; nt < 8; ++nt) {
            int col = n0 + wn + nt * 8 + fc * 2;
            float bv0 = bias[col], bv1 = bias[col + 1];
            float2 v0; v0.x = acc[mt][nt][0] + bv0; v0.y = acc[mt][nt][1] + bv1;
            float2 v1; v1.x = acc[mt][nt][2] + bv0; v1.y = acc[mt][nt][3] + bv1;
            *(float2*)&C[(size_t)row * N + col] = v0;
            *(float2*)&C[(size_t)(row + 8) * N + col] = v1;
        }
    }
}

__global__ __launch_bounds__(128) void gemm_tf32_nt_bias3(
    const float* __restrict__ A,
    const float* __restrict__ W0, const float* __restrict__ W1, const float* __restrict__ W2,
    const float* __restrict__ b0, const float* __restrict__ b1, const float* __restrict__ b2,
    float* __restrict__ C0, float* __restrict__ C1, float* __restrict__ C2,
    int M, int N, int K)
{
    __shared__ unsigned As[2 * 2048];
    __shared__ unsigned Bs[2 * 2048];
    const float* W    = (blockIdx.z == 0) ? W0 : (blockIdx.z == 1) ? W1 : W2;
    const float* bias = (blockIdx.z == 0) ? b0 : (blockIdx.z == 1) ? b1 : b2;
    float* C          = (blockIdx.z == 0) ? C0 : (blockIdx.z == 1) ? C1 : C2;
    gemm_tf32_body(As, Bs, A, W, bias, C, M, N, K);
}

// -------- logits GEMM v3: 128x256 tile, BK=32, 3-stage cp.async ---------
__device__ __forceinline__ unsigned smem_addr_u32(const void* p)
{
    unsigned a;
    asm("{ .reg .u64 t; cvta.to.shared.u64 t, %1; cvt.u32.u64 %0, t; }"
        : "=r"(a) : "l"(p));
    return a;
}

__global__ __launch_bounds__(256) void gemm_tf32_logits(
    const float* __restrict__ A,    // [SB,512]  tf32-rounded
    const float* __restrict__ W,    // [VV,512]  tf32-rounded
    const float* __restrict__ bias,
    float* __restrict__ C)          // [SB,VV]
{
    extern __shared__ unsigned smx[];
    unsigned* As = smx;               // [3][128*32]
    unsigned* Bs = smx + 3 * 4096;    // [3][256*32]

    const int tid  = threadIdx.x;
    const int lane = tid & 31;
    const int warp = tid >> 5;        // 0..7
    const int wm = (warp >> 2) * 64;  // 2 m-warp rows
    const int wn = (warp & 3) * 64;   // 4 n-warp cols
    const int m0 = blockIdx.y * 128;
    const int n0 = blockIdx.x * 256;
    const int fr = lane >> 2;
    const int fc = lane & 3;

    float acc[4][8][4];
#pragma unroll
    for (int mt = 0; mt < 4; ++mt)
#pragma unroll
        for (int nt = 0; nt < 8; ++nt)
#pragma unroll
            for (int q = 0; q < 4; ++q) acc[mt][nt][q] = 0.f;

#define CP_STAGE(buf, k0)                                                     \
    {                                                                         \
        _Pragma("unroll")                                                     \
        for (int it = 0; it < 4; ++it) {                                      \
            int c = tid + it * 256;                                           \
            int r = c >> 3, ch = c & 7;                                       \
            unsigned d = smem_addr_u32(                                       \
                &As[(buf) * 4096 + r * 32 + ((ch ^ (r & 7)) << 2)]);          \
            const float* sp = A + (size_t)(m0 + r) * 512 + (k0) + ch * 4;     \
            asm volatile("cp.async.cg.shared.global [%0], [%1], 16;"          \
                         :: "r"(d), "l"(sp));                                 \
        }                                                                     \
        _Pragma("unroll")                                                     \
        for (int it = 0; it < 8; ++it) {                                      \
            int c = tid + it * 256;                                           \
            int r = c >> 3, ch = c & 7;                                       \
            unsigned d = smem_addr_u32(                                       \
                &Bs[(buf) * 8192 + r * 32 + ((ch ^ (r & 7)) << 2)]);          \
            const float* sp = W + (size_t)(n0 + r) * 512 + (k0) + ch * 4;     \
            asm volatile("cp.async.cg.shared.global [%0], [%1], 16;"          \
                         :: "r"(d), "l"(sp));                                 \
        }                                                                     \
        asm volatile("cp.async.commit_group;");                               \
    }

    // prologue: two stages in flight
    CP_STAGE(0, 0)
    CP_STAGE(1, 32)
    asm volatile("cp.async.wait_group 1;");   // stage 0 ready
    __syncthreads();

    const int nstages = 512 / 32;    // 16
    for (int s = 0; s < nstages; ++s) {
        const int buf = s - (s / 3) * 3;      // s % 3

#pragma unroll
        for (int k8 = 0; k8 < 4; ++k8) {
            const int ch0 = k8 * 2, ch1 = k8 * 2 + 1;
            unsigned af[4][4], bf[8][2];
#pragma unroll
            for (int mt = 0; mt < 4; ++mt) {
                int r1 = wm + mt * 16 + fr;
                int r2 = r1 + 8;
                af[mt][0] = As[buf*4096 + r1*32 + ((ch0 ^ (r1&7)) << 2) + fc];
                af[mt][1] = As[buf*4096 + r2*32 + ((ch0 ^ (r2&7)) << 2) + fc];
                af[mt][2] = As[buf*4096 + r1*32 + ((ch1 ^ (r1&7)) << 2) + fc];
                af[mt][3] = As[buf*4096 + r2*32 + ((ch1 ^ (r2&7)) << 2) + fc];
            }
#pragma unroll
            for (int nt = 0; nt < 8; ++nt) {
                int n = wn + nt * 8 + fr;
                bf[nt][0] = Bs[buf*8192 + n*32 + ((ch0 ^ (n&7)) << 2) + fc];
                bf[nt][1] = Bs[buf*8192 + n*32 + ((ch1 ^ (n&7)) << 2) + fc];
            }
#pragma unroll
            for (int mt = 0; mt < 4; ++mt)
#pragma unroll
                for (int nt = 0; nt < 8; ++nt) {
                    asm volatile(
                        "mma.sync.aligned.m16n8k8.row.col.f32.tf32.tf32.f32 "
                        "{%0,%1,%2,%3}, {%4,%5,%6,%7}, {%8,%9}, {%0,%1,%2,%3};"
                        : "+f"(acc[mt][nt][0]), "+f"(acc[mt][nt][1]),
                          "+f"(acc[mt][nt][2]), "+f"(acc[mt][nt][3])
                        : "r"(af[mt][0]), "r"(af[mt][1]),
                          "r"(af[mt][2]), "r"(af[mt][3]),
                          "r"(bf[nt][0]), "r"(bf[nt][1]));
                }
        }

        if (s + 2 < nstages) {
            const int nbuf = (s + 2) - ((s + 2) / 3) * 3;
            CP_STAGE(nbuf, (s + 2) * 32)
            asm volatile("cp.async.wait_group 1;");  // stage s+1 ready
        } else {
            asm volatile("cp.async.wait_group 0;");  // drain tail
        }
        __syncthreads();
    }
#undef CP_STAGE

#pragma unroll
    for (int mt = 0; mt < 4; ++mt) {
        int row = m0 + wm + mt * 16 + fr;
#pragma unroll
        for (int nt = 0; nt < 8; ++nt) {
            int col = n0 + wn + nt * 8 + fc * 2;
            float bv0 = bias[col], bv1 = bias[col + 1];
            float2 v0; v0.x = acc[mt][nt][0] + bv0; v0.y = acc[mt][nt][1] + bv1;
            float2 v1; v1.x = acc[mt][nt][2] + bv0; v1.y = acc[mt][nt][3] + bv1;
            *(float2*)&C[(size_t)row * VV + col] = v0;
            *(float2*)&C[(size_t)(row + 8) * VV + col] = v1;
        }
    }
}

// ------------- persistent GRU scan v9 (R13/R14 winner, staged) ------------
__device__ __forceinline__ void fma2(unsigned long long& a,
                                     unsigned long long x, unsigned long long h)
{
    asm("fma.rn.f32x2 %0, %1, %2, %0;" : "+l"(a) : "l"(x), "l"(h));
}

__global__ __launch_bounds__(512, 1) void gru_scan_kernel(
    const float* __restrict__ gates,   // [3][SB][HH]
    const float* __restrict__ Wr,
    const float* __restrict__ Wz,
    const float* __restrict__ Wh,
    const float* __restrict__ h0,      // [BB][HH]
    float* __restrict__ hs_out,        // [SS][BB][HH]
    float* __restrict__ hfin)          // [BB][HH] or null
{
    extern __shared__ float sm[];
    float* hsm = sm;                       // [8][HSTRIDE]
    float* red = sm + 8 * HSTRIDE;         // [16][24][33]
    unsigned* sF0 = (unsigned*)(red + 16 * 24 * 33);

    const int tid  = threadIdx.x;
    const int lane = tid & 31;
    const int w    = tid >> 5;             // 0..15 = jl
    const int bid  = blockIdx.x;
    const int jg   = bid >> 2;             // 0..31
    const int bg   = bid & 3;              // 0..3
    const int j    = jg * 16 + w;

    unsigned* flags = &g_flag[bg].v[0];

    if (tid == 0) sF0[0] = flags[jg];

    ulonglong2 wv[3][4];
    {
        const float* W0 = Wr + (size_t)j * HH;
        const float* W1 = Wz + (size_t)j * HH;
        const float* W2 = Wh + (size_t)j * HH;
#pragma unroll
        for (int i = 0; i < 4; ++i) {
            int kof = 4 * lane + 128 * i;
            wv[0][i] = *(const ulonglong2*)&W0[kof];
            wv[1][i] = *(const ulonglong2*)&W1[kof];
            wv[2][i] = *(const ulonglong2*)&W2[kof];
        }
    }
    __syncthreads();
    const unsigned F0 = sF0[0];

    const int b = bg * 8 + (lane & 7);

    float xr = 0.f, xz = 0.f, xh = 0.f;
    if (lane < 8) {
        size_t idx = (size_t)(0 * BB + b) * HH + j;
        xr = __ldcg(&gates[idx]);
        xz = __ldcg(&gates[(size_t)SB * HH + idx]);
        xh = __ldcg(&gates[(size_t)2 * SB * HH + idx]);
    }

    for (int s = 0; s < SS; ++s) {
        const float* hsrc = (s == 0) ? h0 : hs_out + (size_t)(s - 1) * BB * HH;
        float* hdst = hs_out + (size_t)s * BB * HH;

        if (s > 0) {
            if (w == 0) {
                const unsigned target = F0 + (unsigned)s;
                unsigned v;
                bool ok;
                do {
                    asm volatile("ld.acquire.gpu.u32 %0, [%1];"
                                 : "=r"(v) : "l"(flags + lane) : "memory");
                    ok = __all_sync(0xffffffffu, (int)(v - target) >= 0);
                } while (!ok);
            }
            __syncthreads();
        }

#pragma unroll
        for (int it = 0; it < 2; ++it) {
            int c = tid + it * 512;
            int bs = c >> 7;
            int kq = c & 127;
            unsigned dst = (unsigned)__cvta_generic_to_shared(
                &hsm[bs * HSTRIDE + kq * 4]);
            const float* src = hsrc + (size_t)(bg * 8 + bs) * HH + kq * 4;
            asm volatile("cp.async.cg.shared.global [%0], [%1], 16;"
                         :: "r"(dst), "l"(src));
        }
        asm volatile("cp.async.commit_group;");
        asm volatile("cp.async.wait_group 0;");
        __syncthreads();

        unsigned long long acc[3][8];
#pragma unroll
        for (int g = 0; g < 3; ++g)
#pragma unroll
            for (int c = 0; c < 8; ++c) acc[g][c] = 0ULL;

#pragma unroll
        for (int i = 0; i < 4; ++i) {
            const int kof = 4 * lane + 128 * i;
#pragma unroll
            for (int c = 0; c < 8; ++c) {
                ulonglong2 hv = *(const ulonglong2*)&hsm[c * HSTRIDE + kof];
                fma2(acc[0][c], wv[0][i].x, hv.x);
                fma2(acc[0][c], wv[0][i].y, hv.y);
                fma2(acc[1][c], wv[1][i].x, hv.x);
                fma2(acc[1][c], wv[1][i].y, hv.y);
                fma2(acc[2][c], wv[2][i].x, hv.x);
                fma2(acc[2][c], wv[2][i].y, hv.y);
            }
        }

#pragma unroll
        for (int g = 0; g < 3; ++g)
#pragma unroll
            for (int c = 0; c < 8; ++c) {
                float2 f = *(float2*)&acc[g][c];
                red[(w * 24 + g * 8 + c) * 33 + lane] = f.x + f.y;
            }
        __syncwarp();

        float sum = 0.f;
        if (lane < 24) {
            int base = (w * 24 + lane) * 33;
#pragma unroll
            for (int i = 0; i < 32; ++i) sum += red[base + i];
        }
        float s0 = __shfl_sync(0xffffffffu, sum, (lane & 7));
        float s1 = __shfl_sync(0xffffffffu, sum, 8 + (lane & 7));
        float s2 = __shfl_sync(0xffffffffu, sum, 16 + (lane & 7));

        if (lane < 8) {
            float hold = hsm[(lane & 7) * HSTRIDE + j];
            float r  = 1.f / (1.f + __expf(-(xr + s0)));
            float z  = 1.f / (1.f + __expf(-(xz + s1)));
            float hc = tanhf(xh + r * s2);
            float hn = (1.f - z) * hc + z * hold;
            hdst[(size_t)b * HH + j] = hn;
            if (s == SS - 1 && hfin) hfin[(size_t)b * HH + j] = hn;
        }

        if (lane < 8 && s + 1 < SS) {
            size_t idx = (size_t)((s + 1) * BB + b) * HH + j;
            xr = __ldcg(&gates[idx]);
            xz = __ldcg(&gates[(size_t)SB * HH + idx]);
            xh = __ldcg(&gates[(size_t)2 * SB * HH + idx]);
        }

        __syncthreads();
        if (tid == 0) {
            asm volatile("st.release.gpu.u32 [%0], %1;"
                         :: "l"(flags + jg), "r"(F0 + (unsigned)s + 1u)
                         : "memory");
        }
    }
}

// ------------------------------ driver ----------------------------------
extern "C" void kernel_launch(void* const* d_in, const int* in_sizes, int n_in,
                              void* d_out, int out_size)
{
    const int*   inputs = (const int*)d_in[0];
    const float* hidden = (const float*)d_in[1];
    const float* emb    = (const float*)d_in[2];
    const float* Wir    = (const float*)d_in[3];
    const float* bir    = (const float*)d_in[4];
    const float* Wiz    = (const float*)d_in[5];
    const float* biz    = (const float*)d_in[6];
    const float* Wih    = (const float*)d_in[7];
    const float* bih    = (const float*)d_in[8];
    const float* Whr    = (const float*)d_in[9];
    const float* Whz    = (const float*)d_in[10];
    const float* Whh    = (const float*)d_in[11];
    const float* Wout   = (const float*)d_in[12];
    const float* bout   = (const float*)d_in[13];
    float* out = (float*)d_out;

    float *px, *py, *pg, *pwr;
    cudaGetSymbolAddress((void**)&px, g_x);
    cudaGetSymbolAddress((void**)&py, g_y);
    cudaGetSymbolAddress((void**)&pg, g_gates);
    cudaGetSymbolAddress((void**)&pwr, g_wr);

    const size_t logits_elems = (size_t)SB * VV;
    float* hfin_base = nullptr;
    if ((size_t)out_size >= logits_elems + (size_t)LL * BB * HH)
        hfin_base = out + logits_elems;

    const int smem_scan = (8 * HSTRIDE + 16 * 24 * 33) * sizeof(float) + 16;
    cudaFuncSetAttribute(gru_scan_kernel,
                         cudaFuncAttributeMaxDynamicSharedMemorySize, smem_scan);
    const int smem_log = (3 * 4096 + 3 * 8192) * sizeof(unsigned);  // 144KB
    cudaFuncSetAttribute(gemm_tf32_logits,
                         cudaFuncAttributeMaxDynamicSharedMemorySize, smem_log);

    // 0) profiler-window nudge
    nudge_kernel<<<1, 32>>>();

    // 1) embedding
    embed_kernel<<<SB, 128>>>(inputs, emb, px);

    const size_t CHNK = (size_t)SB * HH;
    for (int l = 0; l < LL; ++l) {
        float* in   = (l == 0) ? px : py;
        float* outb = (l == 0) ? py : px;

        // 2) fused input projections (tf32 mma, gate = blockIdx.z)
        dim3 gProj(HH / 128, SB / 128, 3);   // (4, 16, 3)
        gemm_tf32_nt_bias3<<<gProj, 128>>>(
            in,
            Wir + (size_t)l * HH * EE, Wiz + (size_t)l * HH * EE, Wih + (size_t)l * HH * EE,
            bir + l * HH, biz + l * HH, bih + l * HH,
            pg + 0 * CHNK, pg + 1 * CHNK, pg + 2 * CHNK,
            SB, HH, EE);

        // 3) persistent scan over all 64 steps (staged, one-hop flag sync)
        gru_scan_kernel<<<NBLK, 512, smem_scan>>>(
            pg,
            Whr + (size_t)l * HH * HH,
            Whz + (size_t)l * HH * HH,
            Whh + (size_t)l * HH * HH,
            hidden + (size_t)l * BB * HH,
            outb,
            hfin_base ? hfin_base + (size_t)l * BB * HH : nullptr);
    }

    // 4) pre-round logits operands to tf32-rne
    round_tf32_kernel<<<2048, 256>>>(Wout, pwr, VV * HH / 4);
    round_tf32_kernel<<<512, 256>>>(px, px, SB * HH / 4);

    // 5) logits GEMM v3 (3-stage cp.async, 128x256 tile)
    dim3 gLog(VV / 256, SB / 128);   // (125, 16)
    gemm_tf32_logits<<<gLog, 256, smem_log>>>(px, pwr, bout, out);
}